// round 2
// baseline (speedup 1.0000x reference)
#include <cuda_runtime.h>
#include <cuda_bf16.h>

// Problem constants
#define BB   8
#define CC   64
#define HH   256
#define WW   256
#define HWSZ 65536          // 256*256
#define C3   192            // 3*CC

typedef unsigned long long u64;

// Scratch (device globals -- allocation-free rule)
__device__ float g_qkv[(size_t)BB * C3 * HWSZ];   // 402 MB
__device__ float g_att[(size_t)BB * CC * HWSZ];   // 134 MB

// ---------------------------------------------------------------------------
// packed f32x2 helpers (SASS FFMA2 -- ptxas never auto-fuses; PTX-only path)
// ---------------------------------------------------------------------------
__device__ __forceinline__ u64 pack2(float lo, float hi) {
    u64 r;
    asm("mov.b64 %0, {%1, %2};"
        : "=l"(r) : "r"(__float_as_uint(lo)), "r"(__float_as_uint(hi)));
    return r;
}
__device__ __forceinline__ u64 fma2(u64 a, u64 b, u64 c) {
    u64 d;
    asm("fma.rn.f32x2 %0, %1, %2, %3;" : "=l"(d) : "l"(a), "l"(b), "l"(c));
    return d;
}
__device__ __forceinline__ void unpack2(u64 v, float& lo, float& hi) {
    unsigned int l, h;
    asm("mov.b64 {%0, %1}, %2;" : "=r"(l), "=r"(h) : "l"(v));
    lo = __uint_as_float(l);
    hi = __uint_as_float(h);
}

// ---------------------------------------------------------------------------
// K1: qkv = W(192x64) @ x  (1x1 conv over NCHW), f32x2 packed.
// Block: 64 pixels x 192 oc. blockDim 256 = (tx 0..15 -> 4 px, ty 0..15 -> 6
// oc-pairs = 12 oc). Weights pre-packed in smem as (oc_even, oc_odd) u64.
// ---------------------------------------------------------------------------
__global__ __launch_bounds__(256) void qkv1x1_kernel(const float* __restrict__ x,
                                                     const float* __restrict__ w)
{
    __shared__ u64    ws2[64 * 96];     // [ic][oc_pair]  48KB
    __shared__ float4 xs[64 * 16];      // [ic][px4]       4KB

    const int tid = threadIdx.x;

    // Pack W: ws2[ic*96 + p] = { w[2p][ic], w[2p+1][ic] }
    for (int i = tid; i < 64 * 96; i += 256) {
        int ic = i / 96, p = i - (i / 96) * 96;
        ws2[i] = pack2(w[(2 * p) * 64 + ic], w[(2 * p + 1) * 64 + ic]);
    }

    const int base = blockIdx.x * 64;          // global pixel base
    const int b  = base >> 16;
    const int hw = base & 65535;
    const float* xp = x + (b * CC) * HWSZ + hw;

    for (int i = tid; i < 64 * 16; i += 256) {
        int ic = i >> 4, p4 = i & 15;
        xs[i] = *(const float4*)(xp + ic * HWSZ + p4 * 4);
    }
    __syncthreads();

    const int tx = tid & 15, ty = tid >> 4;
    const int ob = ty * 6;                     // oc-pair base (6 pairs = 12 oc)

    u64 acc[6][4];
#pragma unroll
    for (int o = 0; o < 6; o++)
#pragma unroll
        for (int p = 0; p < 4; p++) acc[o][p] = 0ull;

#pragma unroll 4
    for (int ic = 0; ic < 64; ic++) {
        float4 xv = xs[ic * 16 + tx];
        u64 xq0 = pack2(xv.x, xv.x);
        u64 xq1 = pack2(xv.y, xv.y);
        u64 xq2 = pack2(xv.z, xv.z);
        u64 xq3 = pack2(xv.w, xv.w);
        const u64* wp = &ws2[ic * 96 + ob];
#pragma unroll
        for (int o = 0; o < 6; o++) {
            u64 wv = wp[o];
            acc[o][0] = fma2(xq0, wv, acc[o][0]);
            acc[o][1] = fma2(xq1, wv, acc[o][1]);
            acc[o][2] = fma2(xq2, wv, acc[o][2]);
            acc[o][3] = fma2(xq3, wv, acc[o][3]);
        }
    }

    float* op = g_qkv + (size_t)(b * C3) * HWSZ + hw + tx * 4;
#pragma unroll
    for (int o = 0; o < 6; o++) {
        int oc = 2 * (ob + o);
        float4 lo4, hi4;
        unpack2(acc[o][0], lo4.x, hi4.x);
        unpack2(acc[o][1], lo4.y, hi4.y);
        unpack2(acc[o][2], lo4.z, hi4.z);
        unpack2(acc[o][3], lo4.w, hi4.w);
        *(float4*)(op + (size_t)oc * HWSZ)       = lo4;
        *(float4*)(op + (size_t)(oc + 1) * HWSZ) = hi4;
    }
}

// ---------------------------------------------------------------------------
// K2: depthwise 3x3 on (q,k,v) channels + 8x8 circular-conv attention
//     + temperature + v gate.  One block = one (b,c) and a 64x32 pixel tile.
// ---------------------------------------------------------------------------
__global__ __launch_bounds__(256) void attn_kernel(const float* __restrict__ dw_w,
                                                   const float* __restrict__ temperature)
{
    __shared__ float sm[6732];
    __shared__ float dws[27];

    const int tid  = threadIdx.x;
    const int bc   = blockIdx.x >> 5;            // 0..511
    const int tile = blockIdx.x & 31;            // 0..31 (4 across x 8 down)
    const int b = bc >> 6;
    const int c = bc & 63;
    const int tx0 = (tile & 3) * 64;
    const int ty0 = (tile >> 2) * 32;

    if (tid < 27) {
        int ch = tid / 9, tap = tid - ch * 9;
        dws[tid] = dw_w[(c + (ch << 6)) * 9 + tap];
    }

    // Phase A: halo load (34 rows x 66 cols x 3 channels), zero-padded
    for (int i = tid; i < 6732; i += 256) {
        int ch  = i / 2244;
        int rem = i - ch * 2244;
        int hy  = rem / 66;
        int wx  = rem - hy * 66;
        int gh = ty0 + hy - 1;
        int gw = tx0 + wx - 1;
        float v = 0.f;
        if ((unsigned)gh < 256u && (unsigned)gw < 256u)
            v = g_qkv[(size_t)(b * C3 + c + (ch << 6)) * HWSZ + (gh << 8) + gw];
        sm[i] = v;
    }
    __syncthreads();

    // Phase B: depthwise 3x3 into registers (24 outputs per thread)
    float dv[24];
#pragma unroll
    for (int t = 0; t < 24; t++) {
        int i  = tid + (t << 8);
        int ch = i >> 11;
        int p  = i & 2047;
        int r  = p >> 6, cl = p & 63;
        const float* hb = sm + ch * 2244 + r * 66 + cl;
        float a = 0.f;
#pragma unroll
        for (int kh = 0; kh < 3; kh++)
#pragma unroll
            for (int kw = 0; kw < 3; kw++)
                a += hb[kh * 66 + kw] * dws[ch * 9 + kh * 3 + kw];
        dv[t] = a;
    }
    __syncthreads();

    // Phase C: write q/k/v back (aliases halo buffer; index map is exact)
#pragma unroll
    for (int t = 0; t < 24; t++)
        sm[tid + (t << 8)] = dv[t];
    __syncthreads();

    const float* qs = sm;            // [32][64]
    const float* ks = sm + 2048;
    const float* vs = sm + 4096;

    // Phase D: 8x8 circular conv. 32 patches x 8 rows = 256 jobs.
    const int m     = tid & 7;
    const int patch = tid >> 3;
    const int pxi   = patch & 7;
    const int pyi   = patch >> 3;
    const int row0  = pyi * 8;
    const int col0  = pxi * 8;

    float acc[8];
#pragma unroll
    for (int n = 0; n < 8; n++) acc[n] = 0.f;

#pragma unroll
    for (int i = 0; i < 8; i++) {
        int kr = (m - i) & 7;
        const float4* kp = (const float4*)&ks[(row0 + kr) * 64 + col0];
        float4 ka = kp[0], kb = kp[1];
        float kreg[8] = {ka.x, ka.y, ka.z, ka.w, kb.x, kb.y, kb.z, kb.w};
#pragma unroll
        for (int j = 0; j < 8; j++) {
            float qv = qs[(row0 + i) * 64 + col0 + j];
#pragma unroll
            for (int n = 0; n < 8; n++)
                acc[n] += qv * kreg[(n - j) & 7];
        }
    }

    const float tsc = temperature[c];
    const float4* vp = (const float4*)&vs[(row0 + m) * 64 + col0];
    float4 va = vp[0], vb = vp[1];
    float vreg[8] = {va.x, va.y, va.z, va.w, vb.x, vb.y, vb.z, vb.w};

    float4 o0, o1;
    o0.x = acc[0] * tsc * vreg[0];
    o0.y = acc[1] * tsc * vreg[1];
    o0.z = acc[2] * tsc * vreg[2];
    o0.w = acc[3] * tsc * vreg[3];
    o1.x = acc[4] * tsc * vreg[4];
    o1.y = acc[5] * tsc * vreg[5];
    o1.z = acc[6] * tsc * vreg[6];
    o1.w = acc[7] * tsc * vreg[7];

    const int gh  = ty0 + row0 + m;
    const int gw0 = tx0 + col0;
    float* op = g_att + (size_t)bc * HWSZ + (gh << 8) + gw0;
    *(float4*)(op)     = o0;
    *(float4*)(op + 4) = o1;
}

// ---------------------------------------------------------------------------
// K3: out = proj_w(64x64) @ att, f32x2 packed.
// Block: 128 px x 64 oc. blockDim 256 = (tx 0..31 -> 4 px, ty 0..7 -> 4
// oc-pairs = 8 oc).
// ---------------------------------------------------------------------------
__global__ __launch_bounds__(256) void proj_kernel(const float* __restrict__ w,
                                                   float* __restrict__ out)
{
    __shared__ u64    ws2[64 * 32];     // [ic][oc_pair]  16KB
    __shared__ float4 xs[64 * 32];      // [ic][px4]      32KB

    const int tid = threadIdx.x;

    for (int i = tid; i < 64 * 32; i += 256) {
        int ic = i >> 5, p = i & 31;
        ws2[i] = pack2(w[(2 * p) * 64 + ic], w[(2 * p + 1) * 64 + ic]);
    }

    const int base = blockIdx.x * 128;
    const int b  = base >> 16;
    const int hw = base & 65535;
    const float* xp = g_att + (size_t)(b * CC) * HWSZ + hw;

    for (int i = tid; i < 64 * 32; i += 256) {
        int ic = i >> 5, p4 = i & 31;
        xs[i] = *(const float4*)(xp + (size_t)ic * HWSZ + p4 * 4);
    }
    __syncthreads();

    const int tx = tid & 31, ty = tid >> 5;
    const int ob = ty * 4;                      // 4 oc-pairs = 8 oc

    u64 acc[4][4];
#pragma unroll
    for (int o = 0; o < 4; o++)
#pragma unroll
        for (int p = 0; p < 4; p++) acc[o][p] = 0ull;

#pragma unroll 4
    for (int ic = 0; ic < 64; ic++) {
        float4 xv = xs[ic * 32 + tx];
        u64 xq0 = pack2(xv.x, xv.x);
        u64 xq1 = pack2(xv.y, xv.y);
        u64 xq2 = pack2(xv.z, xv.z);
        u64 xq3 = pack2(xv.w, xv.w);
        const u64* wp = &ws2[ic * 32 + ob];
#pragma unroll
        for (int o = 0; o < 4; o++) {
            u64 wv = wp[o];
            acc[o][0] = fma2(xq0, wv, acc[o][0]);
            acc[o][1] = fma2(xq1, wv, acc[o][1]);
            acc[o][2] = fma2(xq2, wv, acc[o][2]);
            acc[o][3] = fma2(xq3, wv, acc[o][3]);
        }
    }

    float* op = out + (size_t)(b * CC) * HWSZ + hw + tx * 4;
#pragma unroll
    for (int o = 0; o < 4; o++) {
        int oc = 2 * (ob + o);
        float4 lo4, hi4;
        unpack2(acc[o][0], lo4.x, hi4.x);
        unpack2(acc[o][1], lo4.y, hi4.y);
        unpack2(acc[o][2], lo4.z, hi4.z);
        unpack2(acc[o][3], lo4.w, hi4.w);
        *(float4*)(op + (size_t)oc * HWSZ)       = lo4;
        *(float4*)(op + (size_t)(oc + 1) * HWSZ) = hi4;
    }
}

// ---------------------------------------------------------------------------
// Launch
// ---------------------------------------------------------------------------
extern "C" void kernel_launch(void* const* d_in, const int* in_sizes, int n_in,
                              void* d_out, int out_size)
{
    const float* x      = (const float*)d_in[0];
    const float* qkv_w  = (const float*)d_in[1];
    const float* dw_w   = (const float*)d_in[2];
    const float* proj_w = (const float*)d_in[3];
    const float* temp   = (const float*)d_in[4];
    float* out = (float*)d_out;

    qkv1x1_kernel<<<8192, 256>>>(x, qkv_w);       // 524288 px / 64
    attn_kernel<<<16384, 256>>>(dw_w, temp);      // 512 (b,c) * 32 tiles
    proj_kernel<<<4096, 256>>>(proj_w, out);      // 524288 px / 128
}

// round 3
// speedup vs baseline: 1.3332x; 1.3332x over previous
#include <cuda_runtime.h>
#include <cuda_bf16.h>

// Problem constants
#define BB   8
#define CC   64
#define HH   256
#define WW   256
#define HWSZ 65536          // 256*256
#define C3   192            // 3*CC

typedef unsigned long long u64;

// Scratch (device globals -- allocation-free rule)
__device__ float g_qkv[(size_t)BB * C3 * HWSZ];   // 402 MB
__device__ float g_att[(size_t)BB * CC * HWSZ];   // 134 MB
__device__ u64   g_wq[64 * 96];                   // packed qkv weights [ic][oc_pair]
__device__ u64   g_wp[64 * 32];                   // packed proj weights [ic][oc_pair]

// ---------------------------------------------------------------------------
// packed f32x2 helpers (SASS FFMA2 -- PTX-only path, ptxas never auto-fuses)
// ---------------------------------------------------------------------------
__device__ __forceinline__ u64 pack2(float lo, float hi) {
    u64 r;
    asm("mov.b64 %0, {%1, %2};"
        : "=l"(r) : "r"(__float_as_uint(lo)), "r"(__float_as_uint(hi)));
    return r;
}
__device__ __forceinline__ u64 fma2(u64 a, u64 b, u64 c) {
    u64 d;
    asm("fma.rn.f32x2 %0, %1, %2, %3;" : "=l"(d) : "l"(a), "l"(b), "l"(c));
    return d;
}
__device__ __forceinline__ void unpack2(u64 v, float& lo, float& hi) {
    unsigned int l, h;
    asm("mov.b64 {%0, %1}, %2;" : "=r"(l), "=r"(h) : "l"(v));
    lo = __uint_as_float(l);
    hi = __uint_as_float(h);
}

// ---------------------------------------------------------------------------
// K0: pack weights once (8192 threads cover 6144 + 2048 pairs)
// ---------------------------------------------------------------------------
__global__ __launch_bounds__(256) void pack_w_kernel(const float* __restrict__ qkv_w,
                                                     const float* __restrict__ proj_w)
{
    int i = blockIdx.x * 256 + threadIdx.x;
    if (i < 64 * 96) {
        int ic = i / 96, p = i - (i / 96) * 96;
        g_wq[i] = pack2(qkv_w[(2 * p) * 64 + ic], qkv_w[(2 * p + 1) * 64 + ic]);
    } else {
        int j = i - 64 * 96;
        int ic = j >> 5, p = j & 31;
        g_wp[j] = pack2(proj_w[(2 * p) * 64 + ic], proj_w[(2 * p + 1) * 64 + ic]);
    }
}

// ---------------------------------------------------------------------------
// K1: qkv = W(192x64) @ x  (1x1 conv over NCHW), f32x2 packed.
// Block: 64 pixels x 192 oc. blockDim 256 = (tx 0..15 -> 4 px, ty 0..15 -> 6
// oc-pairs = 12 oc). Packed weights loaded coalesced from g_wq.
// ---------------------------------------------------------------------------
__global__ __launch_bounds__(256) void qkv1x1_kernel(const float* __restrict__ x)
{
    __shared__ u64    ws2[64 * 96];     // [ic][oc_pair]  48KB
    __shared__ float4 xs[64 * 16];      // [ic][px4]       4KB

    const int tid = threadIdx.x;

    // coalesced copy of pre-packed weights
    for (int i = tid; i < 64 * 96; i += 256)
        ws2[i] = g_wq[i];

    const int base = blockIdx.x * 64;          // global pixel base
    const int b  = base >> 16;
    const int hw = base & 65535;
    const float* xp = x + (size_t)(b * CC) * HWSZ + hw;

    for (int i = tid; i < 64 * 16; i += 256) {
        int ic = i >> 4, p4 = i & 15;
        xs[i] = *(const float4*)(xp + (size_t)ic * HWSZ + p4 * 4);
    }
    __syncthreads();

    const int tx = tid & 15, ty = tid >> 4;
    const int ob = ty * 6;                     // oc-pair base (6 pairs = 12 oc)

    u64 acc[6][4];
#pragma unroll
    for (int o = 0; o < 6; o++)
#pragma unroll
        for (int p = 0; p < 4; p++) acc[o][p] = 0ull;

#pragma unroll 4
    for (int ic = 0; ic < 64; ic++) {
        float4 xv = xs[ic * 16 + tx];
        u64 xq0 = pack2(xv.x, xv.x);
        u64 xq1 = pack2(xv.y, xv.y);
        u64 xq2 = pack2(xv.z, xv.z);
        u64 xq3 = pack2(xv.w, xv.w);
        const u64* wp = &ws2[ic * 96 + ob];
#pragma unroll
        for (int o = 0; o < 6; o++) {
            u64 wv = wp[o];
            acc[o][0] = fma2(xq0, wv, acc[o][0]);
            acc[o][1] = fma2(xq1, wv, acc[o][1]);
            acc[o][2] = fma2(xq2, wv, acc[o][2]);
            acc[o][3] = fma2(xq3, wv, acc[o][3]);
        }
    }

    float* op = g_qkv + (size_t)(b * C3) * HWSZ + hw + tx * 4;
#pragma unroll
    for (int o = 0; o < 6; o++) {
        int oc = 2 * (ob + o);
        float4 lo4, hi4;
        unpack2(acc[o][0], lo4.x, hi4.x);
        unpack2(acc[o][1], lo4.y, hi4.y);
        unpack2(acc[o][2], lo4.z, hi4.z);
        unpack2(acc[o][3], lo4.w, hi4.w);
        *(float4*)(op + (size_t)oc * HWSZ)       = lo4;
        *(float4*)(op + (size_t)(oc + 1) * HWSZ) = hi4;
    }
}

// ---------------------------------------------------------------------------
// K2: depthwise 3x3 on (q,k,v) channels + 8x8 circular-conv attention
//     + temperature + v gate.  One block = one (b,c) and a 64x32 pixel tile.
//     Phase D uses packed f32x2 accumulation.
// ---------------------------------------------------------------------------
__global__ __launch_bounds__(256) void attn_kernel(const float* __restrict__ dw_w,
                                                   const float* __restrict__ temperature)
{
    __shared__ float sm[6732];
    __shared__ float dws[27];

    const int tid  = threadIdx.x;
    const int bc   = blockIdx.x >> 5;            // 0..511
    const int tile = blockIdx.x & 31;            // 0..31 (4 across x 8 down)
    const int b = bc >> 6;
    const int c = bc & 63;
    const int tx0 = (tile & 3) * 64;
    const int ty0 = (tile >> 2) * 32;

    if (tid < 27) {
        int ch = tid / 9, tap = tid - ch * 9;
        dws[tid] = dw_w[(c + (ch << 6)) * 9 + tap];
    }

    // Phase A: halo load (34 rows x 66 cols x 3 channels), zero-padded
    for (int i = tid; i < 6732; i += 256) {
        int ch  = i / 2244;
        int rem = i - ch * 2244;
        int hy  = rem / 66;
        int wx  = rem - hy * 66;
        int gh = ty0 + hy - 1;
        int gw = tx0 + wx - 1;
        float v = 0.f;
        if ((unsigned)gh < 256u && (unsigned)gw < 256u)
            v = g_qkv[(size_t)(b * C3 + c + (ch << 6)) * HWSZ + (gh << 8) + gw];
        sm[i] = v;
    }
    __syncthreads();

    // Phase B: depthwise 3x3 into registers (24 outputs per thread)
    float dv[24];
#pragma unroll
    for (int t = 0; t < 24; t++) {
        int i  = tid + (t << 8);
        int ch = i >> 11;
        int p  = i & 2047;
        int r  = p >> 6, cl = p & 63;
        const float* hb = sm + ch * 2244 + r * 66 + cl;
        float a = 0.f;
#pragma unroll
        for (int kh = 0; kh < 3; kh++)
#pragma unroll
            for (int kw = 0; kw < 3; kw++)
                a += hb[kh * 66 + kw] * dws[ch * 9 + kh * 3 + kw];
        dv[t] = a;
    }
    __syncthreads();

    // Phase C: write q/k/v back (aliases halo buffer; index map is exact)
#pragma unroll
    for (int t = 0; t < 24; t++)
        sm[tid + (t << 8)] = dv[t];
    __syncthreads();

    const float* qs = sm;            // [32][64]
    const float* ks = sm + 2048;
    const float* vs = sm + 4096;

    // Phase D: 8x8 circular conv, f32x2 packed.  32 patches x 8 rows = 256 jobs.
    const int m     = tid & 7;
    const int patch = tid >> 3;
    const int pxi   = patch & 7;
    const int pyi   = patch >> 3;
    const int row0  = pyi * 8;
    const int col0  = pxi * 8;

    u64 accp[4];        // accp[p] = (acc[2p], acc[2p+1])
#pragma unroll
    for (int p = 0; p < 4; p++) accp[p] = 0ull;

#pragma unroll
    for (int i = 0; i < 8; i++) {
        int kr = (m - i) & 7;
        const float4* kp = (const float4*)&ks[(row0 + kr) * 64 + col0];
        float4 ka = kp[0], kb = kp[1];
        float k0 = ka.x, k1 = ka.y, k2 = ka.z, k3 = ka.w;
        float k4 = kb.x, k5 = kb.y, k6 = kb.z, k7 = kb.w;
        // aligned pairs and rotated-by-one pairs of the k row
        u64 ke[4] = { pack2(k0, k1), pack2(k2, k3), pack2(k4, k5), pack2(k6, k7) };
        u64 ko[4] = { pack2(k1, k2), pack2(k3, k4), pack2(k5, k6), pack2(k7, k0) };

        const float4* qp = (const float4*)&qs[(row0 + i) * 64 + col0];
        float4 qa = qp[0], qb = qp[1];
        float qv[8] = { qa.x, qa.y, qa.z, qa.w, qb.x, qb.y, qb.z, qb.w };

#pragma unroll
        for (int j = 0; j < 8; j++) {
            u64 q2 = pack2(qv[j], qv[j]);
            if ((j & 1) == 0) {
                const int s = j >> 1;
#pragma unroll
                for (int p = 0; p < 4; p++)
                    accp[p] = fma2(q2, ke[(p - s) & 3], accp[p]);
            } else {
                const int s = (j + 1) >> 1;
#pragma unroll
                for (int p = 0; p < 4; p++)
                    accp[p] = fma2(q2, ko[(p - s) & 3], accp[p]);
            }
        }
    }

    float acc[8];
#pragma unroll
    for (int p = 0; p < 4; p++) unpack2(accp[p], acc[2 * p], acc[2 * p + 1]);

    const float tsc = temperature[c];
    const float4* vp = (const float4*)&vs[(row0 + m) * 64 + col0];
    float4 va = vp[0], vb = vp[1];
    float vreg[8] = { va.x, va.y, va.z, va.w, vb.x, vb.y, vb.z, vb.w };

    float4 o0, o1;
    o0.x = acc[0] * tsc * vreg[0];
    o0.y = acc[1] * tsc * vreg[1];
    o0.z = acc[2] * tsc * vreg[2];
    o0.w = acc[3] * tsc * vreg[3];
    o1.x = acc[4] * tsc * vreg[4];
    o1.y = acc[5] * tsc * vreg[5];
    o1.z = acc[6] * tsc * vreg[6];
    o1.w = acc[7] * tsc * vreg[7];

    const int gh  = ty0 + row0 + m;
    const int gw0 = tx0 + col0;
    float* op = g_att + (size_t)bc * HWSZ + (gh << 8) + gw0;
    *(float4*)(op)     = o0;
    *(float4*)(op + 4) = o1;
}

// ---------------------------------------------------------------------------
// K3: out = proj_w(64x64) @ att, f32x2 packed, weights from g_wp.
// Block: 128 px x 64 oc. blockDim 256 = (tx 0..31 -> 4 px, ty 0..7 -> 4
// oc-pairs = 8 oc).
// ---------------------------------------------------------------------------
__global__ __launch_bounds__(256) void proj_kernel(float* __restrict__ out)
{
    __shared__ u64    ws2[64 * 32];     // [ic][oc_pair]  16KB
    __shared__ float4 xs[64 * 32];      // [ic][px4]      32KB

    const int tid = threadIdx.x;

    for (int i = tid; i < 64 * 32; i += 256)
        ws2[i] = g_wp[i];

    const int base = blockIdx.x * 128;
    const int b  = base >> 16;
    const int hw = base & 65535;
    const float* xp = g_att + (size_t)(b * CC) * HWSZ + hw;

    for (int i = tid; i < 64 * 32; i += 256) {
        int ic = i >> 5, p4 = i & 31;
        xs[i] = *(const float4*)(xp + (size_t)ic * HWSZ + p4 * 4);
    }
    __syncthreads();

    const int tx = tid & 31, ty = tid >> 5;
    const int ob = ty * 4;                      // 4 oc-pairs = 8 oc

    u64 acc[4][4];
#pragma unroll
    for (int o = 0; o < 4; o++)
#pragma unroll
        for (int p = 0; p < 4; p++) acc[o][p] = 0ull;

#pragma unroll 4
    for (int ic = 0; ic < 64; ic++) {
        float4 xv = xs[ic * 32 + tx];
        u64 xq0 = pack2(xv.x, xv.x);
        u64 xq1 = pack2(xv.y, xv.y);
        u64 xq2 = pack2(xv.z, xv.z);
        u64 xq3 = pack2(xv.w, xv.w);
        const u64* wp = &ws2[ic * 32 + ob];
#pragma unroll
        for (int o = 0; o < 4; o++) {
            u64 wv = wp[o];
            acc[o][0] = fma2(xq0, wv, acc[o][0]);
            acc[o][1] = fma2(xq1, wv, acc[o][1]);
            acc[o][2] = fma2(xq2, wv, acc[o][2]);
            acc[o][3] = fma2(xq3, wv, acc[o][3]);
        }
    }

    float* op = out + (size_t)(b * CC) * HWSZ + hw + tx * 4;
#pragma unroll
    for (int o = 0; o < 4; o++) {
        int oc = 2 * (ob + o);
        float4 lo4, hi4;
        unpack2(acc[o][0], lo4.x, hi4.x);
        unpack2(acc[o][1], lo4.y, hi4.y);
        unpack2(acc[o][2], lo4.z, hi4.z);
        unpack2(acc[o][3], lo4.w, hi4.w);
        *(float4*)(op + (size_t)oc * HWSZ)       = lo4;
        *(float4*)(op + (size_t)(oc + 1) * HWSZ) = hi4;
    }
}

// ---------------------------------------------------------------------------
// Launch
// ---------------------------------------------------------------------------
extern "C" void kernel_launch(void* const* d_in, const int* in_sizes, int n_in,
                              void* d_out, int out_size)
{
    const float* x      = (const float*)d_in[0];
    const float* qkv_w  = (const float*)d_in[1];
    const float* dw_w   = (const float*)d_in[2];
    const float* proj_w = (const float*)d_in[3];
    const float* temp   = (const float*)d_in[4];
    float* out = (float*)d_out;

    pack_w_kernel<<<32, 256>>>(qkv_w, proj_w);    // 8192 threads: 6144 + 2048 pairs
    qkv1x1_kernel<<<8192, 256>>>(x);              // 524288 px / 64
    attn_kernel<<<16384, 256>>>(dw_w, temp);      // 512 (b,c) * 32 tiles
    proj_kernel<<<4096, 256>>>(out);              // 524288 px / 128
}

// round 4
// speedup vs baseline: 1.4284x; 1.0713x over previous
#include <cuda_runtime.h>
#include <cuda_bf16.h>

// Problem constants
#define BB   8
#define CC   64
#define HH   256
#define WW   256
#define HWSZ 65536          // 256*256
#define C3   192            // 3*CC

typedef unsigned long long u64;

// Scratch (device globals -- allocation-free rule)
__device__ float g_qkv[(size_t)BB * C3 * HWSZ];   // 402 MB
__device__ float g_att[(size_t)BB * CC * HWSZ];   // 134 MB
__device__ u64   g_wq[64 * 96];                   // packed qkv weights [ic][oc_pair]
__device__ u64   g_wp[64 * 32];                   // packed proj weights [ic][oc_pair]

// ---------------------------------------------------------------------------
// packed f32x2 helpers (SASS FFMA2 -- PTX-only path, ptxas never auto-fuses)
// ---------------------------------------------------------------------------
__device__ __forceinline__ u64 pack2(float lo, float hi) {
    u64 r;
    asm("mov.b64 %0, {%1, %2};"
        : "=l"(r) : "r"(__float_as_uint(lo)), "r"(__float_as_uint(hi)));
    return r;
}
__device__ __forceinline__ u64 fma2(u64 a, u64 b, u64 c) {
    u64 d;
    asm("fma.rn.f32x2 %0, %1, %2, %3;" : "=l"(d) : "l"(a), "l"(b), "l"(c));
    return d;
}
__device__ __forceinline__ void unpack2(u64 v, float& lo, float& hi) {
    unsigned int l, h;
    asm("mov.b64 {%0, %1}, %2;" : "=r"(l), "=r"(h) : "l"(v));
    lo = __uint_as_float(l);
    hi = __uint_as_float(h);
}

// ---------------------------------------------------------------------------
// K0: pack weights once (8192 threads cover 6144 + 2048 pairs)
// ---------------------------------------------------------------------------
__global__ __launch_bounds__(256) void pack_w_kernel(const float* __restrict__ qkv_w,
                                                     const float* __restrict__ proj_w)
{
    int i = blockIdx.x * 256 + threadIdx.x;
    if (i < 64 * 96) {
        int ic = i / 96, p = i - (i / 96) * 96;
        g_wq[i] = pack2(qkv_w[(2 * p) * 64 + ic], qkv_w[(2 * p + 1) * 64 + ic]);
    } else {
        int j = i - 64 * 96;
        int ic = j >> 5, p = j & 31;
        g_wp[j] = pack2(proj_w[(2 * p) * 64 + ic], proj_w[(2 * p + 1) * 64 + ic]);
    }
}

// ---------------------------------------------------------------------------
// K1: qkv = W(192x64) @ x  (1x1 conv over NCHW), f32x2 packed.
// Block: 64 pixels x 192 oc. blockDim 256 = (tx 0..15 -> 4 px, ty 0..15 -> 6
// oc-pairs = 12 oc). Packed weights loaded coalesced from g_wq.
// ---------------------------------------------------------------------------
__global__ __launch_bounds__(256) void qkv1x1_kernel(const float* __restrict__ x)
{
    __shared__ u64    ws2[64 * 96];     // [ic][oc_pair]  48KB
    __shared__ float4 xs[64 * 16];      // [ic][px4]       4KB

    const int tid = threadIdx.x;

    for (int i = tid; i < 64 * 96; i += 256)
        ws2[i] = g_wq[i];

    const int base = blockIdx.x * 64;          // global pixel base
    const int b  = base >> 16;
    const int hw = base & 65535;
    const float* xp = x + (size_t)(b * CC) * HWSZ + hw;

    for (int i = tid; i < 64 * 16; i += 256) {
        int ic = i >> 4, p4 = i & 15;
        xs[i] = *(const float4*)(xp + (size_t)ic * HWSZ + p4 * 4);
    }
    __syncthreads();

    const int tx = tid & 15, ty = tid >> 4;
    const int ob = ty * 6;                     // oc-pair base (6 pairs = 12 oc)

    u64 acc[6][4];
#pragma unroll
    for (int o = 0; o < 6; o++)
#pragma unroll
        for (int p = 0; p < 4; p++) acc[o][p] = 0ull;

#pragma unroll 4
    for (int ic = 0; ic < 64; ic++) {
        float4 xv = xs[ic * 16 + tx];
        u64 xq0 = pack2(xv.x, xv.x);
        u64 xq1 = pack2(xv.y, xv.y);
        u64 xq2 = pack2(xv.z, xv.z);
        u64 xq3 = pack2(xv.w, xv.w);
        const u64* wp = &ws2[ic * 96 + ob];
#pragma unroll
        for (int o = 0; o < 6; o++) {
            u64 wv = wp[o];
            acc[o][0] = fma2(xq0, wv, acc[o][0]);
            acc[o][1] = fma2(xq1, wv, acc[o][1]);
            acc[o][2] = fma2(xq2, wv, acc[o][2]);
            acc[o][3] = fma2(xq3, wv, acc[o][3]);
        }
    }

    float* op = g_qkv + (size_t)(b * C3) * HWSZ + hw + tx * 4;
#pragma unroll
    for (int o = 0; o < 6; o++) {
        int oc = 2 * (ob + o);
        float4 lo4, hi4;
        unpack2(acc[o][0], lo4.x, hi4.x);
        unpack2(acc[o][1], lo4.y, hi4.y);
        unpack2(acc[o][2], lo4.z, hi4.z);
        unpack2(acc[o][3], lo4.w, hi4.w);
        *(float4*)(op + (size_t)oc * HWSZ)       = lo4;
        *(float4*)(op + (size_t)(oc + 1) * HWSZ) = hi4;
    }
}

// ---------------------------------------------------------------------------
// K2: depthwise 3x3 (f32x2 sliding window) + 8x8 circular-conv attention
//     + temperature + v gate.  One block = one (b,c) and a 64x32 pixel tile.
//     q/k/v smem layout uses row stride 68 floats -> conflict-free phase D.
// ---------------------------------------------------------------------------
#define QKV_STRIDE 68
#define QKV_CH     2176        // 32 * 68
#define QOFF 0
#define KOFF 2176
#define VOFF 4352

__global__ __launch_bounds__(256) void attn_kernel(const float* __restrict__ dw_w,
                                                   const float* __restrict__ temperature)
{
    __shared__ float sm[6732];          // phase A: halo (3 x 34 x 66); phase C/D: q/k/v (3 x 2176)
    __shared__ u64   dws2[27];          // (w,w) packed depthwise taps

    const int tid  = threadIdx.x;
    const int bc   = blockIdx.x >> 5;            // 0..511
    const int tile = blockIdx.x & 31;            // 0..31 (4 across x 8 down)
    const int b = bc >> 6;
    const int c = bc & 63;
    const int tx0 = (tile & 3) * 64;
    const int ty0 = (tile >> 2) * 32;

    if (tid < 27) {
        int ch = tid / 9, tap = tid - ch * 9;
        float wv = dw_w[(c + (ch << 6)) * 9 + tap];
        dws2[tid] = pack2(wv, wv);
    }

    // Phase A: halo load (34 rows x 66 cols x 3 channels), zero-padded
    for (int i = tid; i < 6732; i += 256) {
        int ch  = i / 2244;
        int rem = i - ch * 2244;
        int hy  = rem / 66;
        int wx  = rem - hy * 66;
        int gh = ty0 + hy - 1;
        int gw = tx0 + wx - 1;
        float v = 0.f;
        if ((unsigned)gh < 256u && (unsigned)gw < 256u)
            v = g_qkv[(size_t)(b * C3 + c + (ch << 6)) * HWSZ + (gh << 8) + gw];
        sm[i] = v;
    }
    __syncthreads();

    // Phase B: depthwise 3x3, f32x2 column pairs with vertical sliding window.
    // 192 jobs: (ch 0..2) x (col-pair 0..31) x (row-group 0..1 of 16 rows).
    u64 acc2[16];
    const int jch = tid >> 6;           // valid when tid < 192
    const int jrem = tid & 63;
    const int jc   = (jrem & 31) * 2;   // output col (even)
    const int jr0  = (jrem >> 5) * 16;  // output row base
    if (tid < 192) {
#pragma unroll
        for (int i = 0; i < 16; i++) acc2[i] = 0ull;
        const float* hbase = sm + jch * 2244 + jr0 * 66 + jc;
        const u64* w2 = &dws2[jch * 9];
#pragma unroll
        for (int hy = 0; hy < 18; hy++) {
            u64 A = *(const u64*)(hbase + hy * 66);       // (h[c], h[c+1])
            u64 B = *(const u64*)(hbase + hy * 66 + 2);   // (h[c+2], h[c+3])
            float alo, ahi, blo, bhi;
            unpack2(A, alo, ahi);
            unpack2(B, blo, bhi);
            u64 M1 = pack2(ahi, blo);                      // (h[c+1], h[c+2])
#pragma unroll
            for (int kh = 0; kh < 3; kh++) {
                int r = hy - kh;
                if (r >= 0 && r < 16) {
                    acc2[r] = fma2(A,  w2[kh * 3 + 0], acc2[r]);
                    acc2[r] = fma2(M1, w2[kh * 3 + 1], acc2[r]);
                    acc2[r] = fma2(B,  w2[kh * 3 + 2], acc2[r]);
                }
            }
        }
    }
    __syncthreads();

    // Phase C: store q/k/v in stride-68 layout
    if (tid < 192) {
        float* dst = sm + jch * QKV_CH + jr0 * QKV_STRIDE + jc;
#pragma unroll
        for (int i = 0; i < 16; i++)
            *(u64*)(dst + i * QKV_STRIDE) = acc2[i];
    }
    __syncthreads();

    const float* qs = sm + QOFF;        // [32][68]
    const float* ks = sm + KOFF;
    const float* vs = sm + VOFF;

    // Phase D: 8x8 circular conv, f32x2 packed.  32 patches x 8 rows = 256 jobs.
    const int m     = tid & 7;
    const int patch = tid >> 3;
    const int pxi   = patch & 7;
    const int pyi   = patch >> 3;
    const int row0  = pyi * 8;
    const int col0  = pxi * 8;

    u64 accp[4];        // accp[p] = (acc[2p], acc[2p+1])
#pragma unroll
    for (int p = 0; p < 4; p++) accp[p] = 0ull;

#pragma unroll
    for (int i = 0; i < 8; i++) {
        int kr = (m - i) & 7;
        const float4* kp = (const float4*)&ks[(row0 + kr) * QKV_STRIDE + col0];
        float4 ka = kp[0], kb = kp[1];
        float k0 = ka.x, k1 = ka.y, k2 = ka.z, k3 = ka.w;
        float k4 = kb.x, k5 = kb.y, k6 = kb.z, k7 = kb.w;
        u64 ke[4] = { pack2(k0, k1), pack2(k2, k3), pack2(k4, k5), pack2(k6, k7) };
        u64 ko[4] = { pack2(k1, k2), pack2(k3, k4), pack2(k5, k6), pack2(k7, k0) };

        const float4* qp = (const float4*)&qs[(row0 + i) * QKV_STRIDE + col0];
        float4 qa = qp[0], qb = qp[1];
        float qv[8] = { qa.x, qa.y, qa.z, qa.w, qb.x, qb.y, qb.z, qb.w };

#pragma unroll
        for (int j = 0; j < 8; j++) {
            u64 q2 = pack2(qv[j], qv[j]);
            if ((j & 1) == 0) {
                const int s = j >> 1;
#pragma unroll
                for (int p = 0; p < 4; p++)
                    accp[p] = fma2(q2, ke[(p - s) & 3], accp[p]);
            } else {
                const int s = (j + 1) >> 1;
#pragma unroll
                for (int p = 0; p < 4; p++)
                    accp[p] = fma2(q2, ko[(p - s) & 3], accp[p]);
            }
        }
    }

    float acc[8];
#pragma unroll
    for (int p = 0; p < 4; p++) unpack2(accp[p], acc[2 * p], acc[2 * p + 1]);

    const float tsc = temperature[c];
    const float4* vp = (const float4*)&vs[(row0 + m) * QKV_STRIDE + col0];
    float4 va = vp[0], vb = vp[1];
    float vreg[8] = { va.x, va.y, va.z, va.w, vb.x, vb.y, vb.z, vb.w };

    float4 o0, o1;
    o0.x = acc[0] * tsc * vreg[0];
    o0.y = acc[1] * tsc * vreg[1];
    o0.z = acc[2] * tsc * vreg[2];
    o0.w = acc[3] * tsc * vreg[3];
    o1.x = acc[4] * tsc * vreg[4];
    o1.y = acc[5] * tsc * vreg[5];
    o1.z = acc[6] * tsc * vreg[6];
    o1.w = acc[7] * tsc * vreg[7];

    const int gh  = ty0 + row0 + m;
    const int gw0 = tx0 + col0;
    float* op = g_att + (size_t)bc * HWSZ + (gh << 8) + gw0;
    *(float4*)(op)     = o0;
    *(float4*)(op + 4) = o1;
}

// ---------------------------------------------------------------------------
// K3: out = proj_w(64x64) @ att, f32x2 packed, weights from g_wp.
// Block: 128 px x 64 oc. blockDim 256 = (tx 0..31 -> 4 px, ty 0..7 -> 4
// oc-pairs = 8 oc).
// ---------------------------------------------------------------------------
__global__ __launch_bounds__(256) void proj_kernel(float* __restrict__ out)
{
    __shared__ u64    ws2[64 * 32];     // [ic][oc_pair]  16KB
    __shared__ float4 xs[64 * 32];      // [ic][px4]      32KB

    const int tid = threadIdx.x;

    for (int i = tid; i < 64 * 32; i += 256)
        ws2[i] = g_wp[i];

    const int base = blockIdx.x * 128;
    const int b  = base >> 16;
    const int hw = base & 65535;
    const float* xp = g_att + (size_t)(b * CC) * HWSZ + hw;

    for (int i = tid; i < 64 * 32; i += 256) {
        int ic = i >> 5, p4 = i & 31;
        xs[i] = *(const float4*)(xp + (size_t)ic * HWSZ + p4 * 4);
    }
    __syncthreads();

    const int tx = tid & 31, ty = tid >> 5;
    const int ob = ty * 4;                      // 4 oc-pairs = 8 oc

    u64 acc[4][4];
#pragma unroll
    for (int o = 0; o < 4; o++)
#pragma unroll
        for (int p = 0; p < 4; p++) acc[o][p] = 0ull;

#pragma unroll 4
    for (int ic = 0; ic < 64; ic++) {
        float4 xv = xs[ic * 32 + tx];
        u64 xq0 = pack2(xv.x, xv.x);
        u64 xq1 = pack2(xv.y, xv.y);
        u64 xq2 = pack2(xv.z, xv.z);
        u64 xq3 = pack2(xv.w, xv.w);
        const u64* wp = &ws2[ic * 32 + ob];
#pragma unroll
        for (int o = 0; o < 4; o++) {
            u64 wv = wp[o];
            acc[o][0] = fma2(xq0, wv, acc[o][0]);
            acc[o][1] = fma2(xq1, wv, acc[o][1]);
            acc[o][2] = fma2(xq2, wv, acc[o][2]);
            acc[o][3] = fma2(xq3, wv, acc[o][3]);
        }
    }

    float* op = out + (size_t)(b * CC) * HWSZ + hw + tx * 4;
#pragma unroll
    for (int o = 0; o < 4; o++) {
        int oc = 2 * (ob + o);
        float4 lo4, hi4;
        unpack2(acc[o][0], lo4.x, hi4.x);
        unpack2(acc[o][1], lo4.y, hi4.y);
        unpack2(acc[o][2], lo4.z, hi4.z);
        unpack2(acc[o][3], lo4.w, hi4.w);
        *(float4*)(op + (size_t)oc * HWSZ)       = lo4;
        *(float4*)(op + (size_t)(oc + 1) * HWSZ) = hi4;
    }
}

// ---------------------------------------------------------------------------
// Launch
// ---------------------------------------------------------------------------
extern "C" void kernel_launch(void* const* d_in, const int* in_sizes, int n_in,
                              void* d_out, int out_size)
{
    const float* x      = (const float*)d_in[0];
    const float* qkv_w  = (const float*)d_in[1];
    const float* dw_w   = (const float*)d_in[2];
    const float* proj_w = (const float*)d_in[3];
    const float* temp   = (const float*)d_in[4];
    float* out = (float*)d_out;

    pack_w_kernel<<<32, 256>>>(qkv_w, proj_w);    // 8192 threads: 6144 + 2048 pairs
    qkv1x1_kernel<<<8192, 256>>>(x);              // 524288 px / 64
    attn_kernel<<<16384, 256>>>(dw_w, temp);      // 512 (b,c) * 32 tiles
    proj_kernel<<<4096, 256>>>(out);              // 524288 px / 128
}

// round 5
// speedup vs baseline: 1.9630x; 1.3743x over previous
#include <cuda_runtime.h>
#include <cuda_bf16.h>
#include <cuda_fp16.h>

// Problem constants
#define BB   8
#define CC   64
#define HH   256
#define WW   256
#define HWSZ 65536          // 256*256
#define C3   192            // 3*CC

typedef unsigned long long u64;

// Scratch (device globals -- allocation-free rule).  fp16 storage, fp32 math.
__device__ unsigned short g_qkvh[(size_t)BB * C3 * HWSZ];  // 201 MB
__device__ unsigned short g_atth[(size_t)BB * CC * HWSZ];  //  67 MB
__device__ u64 g_wq[64 * 96];                   // packed qkv weights [ic][oc_pair]
__device__ u64 g_wp[64 * 32];                   // packed proj weights [ic][oc_pair]

// ---------------------------------------------------------------------------
// packed f32x2 helpers (SASS FFMA2 -- PTX-only path, ptxas never auto-fuses)
// ---------------------------------------------------------------------------
__device__ __forceinline__ u64 pack2(float lo, float hi) {
    u64 r;
    asm("mov.b64 %0, {%1, %2};"
        : "=l"(r) : "r"(__float_as_uint(lo)), "r"(__float_as_uint(hi)));
    return r;
}
__device__ __forceinline__ u64 fma2(u64 a, u64 b, u64 c) {
    u64 d;
    asm("fma.rn.f32x2 %0, %1, %2, %3;" : "=l"(d) : "l"(a), "l"(b), "l"(c));
    return d;
}
__device__ __forceinline__ void unpack2(u64 v, float& lo, float& hi) {
    unsigned int l, h;
    asm("mov.b64 {%0, %1}, %2;" : "=r"(l), "=r"(h) : "l"(v));
    lo = __uint_as_float(l);
    hi = __uint_as_float(h);
}
__device__ __forceinline__ unsigned h2u(__half2 h) { return *(unsigned*)&h; }
__device__ __forceinline__ u64 f4_to_h4(float4 v) {
    unsigned a = h2u(__floats2half2_rn(v.x, v.y));
    unsigned b = h2u(__floats2half2_rn(v.z, v.w));
    return ((u64)b << 32) | a;
}

// ---------------------------------------------------------------------------
// K0: pack weights once (8192 threads cover 6144 + 2048 pairs)
// ---------------------------------------------------------------------------
__global__ __launch_bounds__(256) void pack_w_kernel(const float* __restrict__ qkv_w,
                                                     const float* __restrict__ proj_w)
{
    int i = blockIdx.x * 256 + threadIdx.x;
    if (i < 64 * 96) {
        int ic = i / 96, p = i - (i / 96) * 96;
        g_wq[i] = pack2(qkv_w[(2 * p) * 64 + ic], qkv_w[(2 * p + 1) * 64 + ic]);
    } else {
        int j = i - 64 * 96;
        int ic = j >> 5, p = j & 31;
        g_wp[j] = pack2(proj_w[(2 * p) * 64 + ic], proj_w[(2 * p + 1) * 64 + ic]);
    }
}

// ---------------------------------------------------------------------------
// K1: qkv = W(192x64) @ x  (1x1 conv over NCHW), f32x2 packed, fp16 output.
// Block: 64 pixels x 192 oc. blockDim 256 = (tx 0..15 -> 4 px, ty 0..15 -> 6
// oc-pairs = 12 oc).
// ---------------------------------------------------------------------------
__global__ __launch_bounds__(256) void qkv1x1_kernel(const float* __restrict__ x)
{
    __shared__ u64    ws2[64 * 96];     // [ic][oc_pair]  48KB
    __shared__ float4 xs[64 * 16];      // [ic][px4]       4KB

    const int tid = threadIdx.x;

    for (int i = tid; i < 64 * 96; i += 256)
        ws2[i] = g_wq[i];

    const int base = blockIdx.x * 64;          // global pixel base
    const int b  = base >> 16;
    const int hw = base & 65535;
    const float* xp = x + (size_t)(b * CC) * HWSZ + hw;

    for (int i = tid; i < 64 * 16; i += 256) {
        int ic = i >> 4, p4 = i & 15;
        xs[i] = *(const float4*)(xp + (size_t)ic * HWSZ + p4 * 4);
    }
    __syncthreads();

    const int tx = tid & 15, ty = tid >> 4;
    const int ob = ty * 6;                     // oc-pair base (6 pairs = 12 oc)

    u64 acc[6][4];
#pragma unroll
    for (int o = 0; o < 6; o++)
#pragma unroll
        for (int p = 0; p < 4; p++) acc[o][p] = 0ull;

#pragma unroll 4
    for (int ic = 0; ic < 64; ic++) {
        float4 xv = xs[ic * 16 + tx];
        u64 xq0 = pack2(xv.x, xv.x);
        u64 xq1 = pack2(xv.y, xv.y);
        u64 xq2 = pack2(xv.z, xv.z);
        u64 xq3 = pack2(xv.w, xv.w);
        const u64* wp = &ws2[ic * 96 + ob];
#pragma unroll
        for (int o = 0; o < 6; o++) {
            u64 wv = wp[o];
            acc[o][0] = fma2(xq0, wv, acc[o][0]);
            acc[o][1] = fma2(xq1, wv, acc[o][1]);
            acc[o][2] = fma2(xq2, wv, acc[o][2]);
            acc[o][3] = fma2(xq3, wv, acc[o][3]);
        }
    }

    __half* op = (__half*)g_qkvh + (size_t)(b * C3) * HWSZ + hw + tx * 4;
#pragma unroll
    for (int o = 0; o < 6; o++) {
        int oc = 2 * (ob + o);
        float4 lo4, hi4;
        unpack2(acc[o][0], lo4.x, hi4.x);
        unpack2(acc[o][1], lo4.y, hi4.y);
        unpack2(acc[o][2], lo4.z, hi4.z);
        unpack2(acc[o][3], lo4.w, hi4.w);
        *(u64*)(op + (size_t)oc * HWSZ)       = f4_to_h4(lo4);
        *(u64*)(op + (size_t)(oc + 1) * HWSZ) = f4_to_h4(hi4);
    }
}

// ---------------------------------------------------------------------------
// K2: depthwise 3x3 (f32x2 sliding window) + 8x8 circular-conv attention
//     + temperature + v gate.  One block = one (b,c) and a 64x32 pixel tile.
//     Phase A loads fp16 qkv with uint4 vectors; q/k/v stride-68 layout.
// ---------------------------------------------------------------------------
#define QKV_STRIDE 68
#define QKV_CH     2176        // 32 * 68
#define QOFF 0
#define KOFF 2176
#define VOFF 4352

__global__ __launch_bounds__(256) void attn_kernel(const float* __restrict__ dw_w,
                                                   const float* __restrict__ temperature)
{
    __shared__ float sm[6732];          // phase A: halo (3 x 34 x 66); phase C/D: q/k/v (3 x 2176)
    __shared__ u64   dws2[27];          // (w,w) packed depthwise taps

    const int tid  = threadIdx.x;
    const int bc   = blockIdx.x >> 5;            // 0..511
    const int tile = blockIdx.x & 31;            // 0..31 (4 across x 8 down)
    const int b = bc >> 6;
    const int c = bc & 63;
    const int tx0 = (tile & 3) * 64;
    const int ty0 = (tile >> 2) * 32;

    if (tid < 27) {
        int ch = tid / 9, tap = tid - ch * 9;
        float wv = dw_w[(c + (ch << 6)) * 9 + tap];
        dws2[tid] = pack2(wv, wv);
    }

    const __half* qbase = (const __half*)g_qkvh;

    // Phase A interior: 816 vector jobs (3 ch x 34 rows x 8 uint4/row)
    for (int i = tid; i < 816; i += 256) {
        int ch  = i / 272;
        int rem = i - ch * 272;
        int hy  = rem >> 3, v8 = rem & 7;
        int gh  = ty0 + hy - 1;
        float f0, f1, f2, f3, f4, f5, f6, f7;
        if ((unsigned)gh < 256u) {
            const __half* gp = qbase + (size_t)(b * C3 + c + (ch << 6)) * HWSZ
                             + (gh << 8) + tx0 + v8 * 8;
            uint4 u = *(const uint4*)gp;
            const __half2* hp = (const __half2*)&u;
            float2 a = __half22float2(hp[0]);
            float2 bb = __half22float2(hp[1]);
            float2 cc = __half22float2(hp[2]);
            float2 dd = __half22float2(hp[3]);
            f0 = a.x;  f1 = a.y;  f2 = bb.x; f3 = bb.y;
            f4 = cc.x; f5 = cc.y; f6 = dd.x; f7 = dd.y;
        } else {
            f0 = f1 = f2 = f3 = f4 = f5 = f6 = f7 = 0.f;
        }
        float* sp = sm + ch * 2244 + hy * 66 + 1 + v8 * 8;
        sp[0] = f0;
        *(float2*)(sp + 1) = make_float2(f1, f2);
        *(float2*)(sp + 3) = make_float2(f3, f4);
        *(float2*)(sp + 5) = make_float2(f5, f6);
        sp[7] = f7;
    }
    // Phase A edges: 204 jobs (3 ch x 34 rows x 2 sides)
    if (tid < 204) {
        int rc = tid >> 1, side = tid & 1;
        int ch = rc / 34, hy = rc - ch * 34;
        int gh = ty0 + hy - 1;
        int gw = side ? (tx0 + 64) : (tx0 - 1);
        float v = 0.f;
        if ((unsigned)gh < 256u && (unsigned)gw < 256u)
            v = __half2float(qbase[(size_t)(b * C3 + c + (ch << 6)) * HWSZ + (gh << 8) + gw]);
        sm[ch * 2244 + hy * 66 + (side ? 65 : 0)] = v;
    }
    __syncthreads();

    // Phase B: depthwise 3x3, f32x2 column pairs with vertical sliding window.
    // 192 jobs: (ch 0..2) x (col-pair 0..31) x (row-group 0..1 of 16 rows).
    u64 acc2[16];
    const int jch = tid >> 6;           // valid when tid < 192
    const int jrem = tid & 63;
    const int jc   = (jrem & 31) * 2;   // output col (even)
    const int jr0  = (jrem >> 5) * 16;  // output row base
    if (tid < 192) {
#pragma unroll
        for (int i = 0; i < 16; i++) acc2[i] = 0ull;
        const float* hbase = sm + jch * 2244 + jr0 * 66 + jc;
        const u64* w2 = &dws2[jch * 9];
#pragma unroll
        for (int hy = 0; hy < 18; hy++) {
            u64 A = *(const u64*)(hbase + hy * 66);       // (h[c], h[c+1])
            u64 B = *(const u64*)(hbase + hy * 66 + 2);   // (h[c+2], h[c+3])
            float alo, ahi, blo, bhi;
            unpack2(A, alo, ahi);
            unpack2(B, blo, bhi);
            u64 M1 = pack2(ahi, blo);                      // (h[c+1], h[c+2])
#pragma unroll
            for (int kh = 0; kh < 3; kh++) {
                int r = hy - kh;
                if (r >= 0 && r < 16) {
                    acc2[r] = fma2(A,  w2[kh * 3 + 0], acc2[r]);
                    acc2[r] = fma2(M1, w2[kh * 3 + 1], acc2[r]);
                    acc2[r] = fma2(B,  w2[kh * 3 + 2], acc2[r]);
                }
            }
        }
    }
    __syncthreads();

    // Phase C: store q/k/v in stride-68 layout
    if (tid < 192) {
        float* dst = sm + jch * QKV_CH + jr0 * QKV_STRIDE + jc;
#pragma unroll
        for (int i = 0; i < 16; i++)
            *(u64*)(dst + i * QKV_STRIDE) = acc2[i];
    }
    __syncthreads();

    const float* qs = sm + QOFF;        // [32][68]
    const float* ks = sm + KOFF;
    const float* vs = sm + VOFF;

    // Phase D: 8x8 circular conv, f32x2 packed.  32 patches x 8 rows = 256 jobs.
    const int m     = tid & 7;
    const int patch = tid >> 3;
    const int pxi   = patch & 7;
    const int pyi   = patch >> 3;
    const int row0  = pyi * 8;
    const int col0  = pxi * 8;

    u64 accp[4];        // accp[p] = (acc[2p], acc[2p+1])
#pragma unroll
    for (int p = 0; p < 4; p++) accp[p] = 0ull;

#pragma unroll
    for (int i = 0; i < 8; i++) {
        int kr = (m - i) & 7;
        const float4* kp = (const float4*)&ks[(row0 + kr) * QKV_STRIDE + col0];
        float4 ka = kp[0], kb = kp[1];
        float k0 = ka.x, k1 = ka.y, k2 = ka.z, k3 = ka.w;
        float k4 = kb.x, k5 = kb.y, k6 = kb.z, k7 = kb.w;
        u64 ke[4] = { pack2(k0, k1), pack2(k2, k3), pack2(k4, k5), pack2(k6, k7) };
        u64 ko[4] = { pack2(k1, k2), pack2(k3, k4), pack2(k5, k6), pack2(k7, k0) };

        const float4* qp = (const float4*)&qs[(row0 + i) * QKV_STRIDE + col0];
        float4 qa = qp[0], qb = qp[1];
        float qv[8] = { qa.x, qa.y, qa.z, qa.w, qb.x, qb.y, qb.z, qb.w };

#pragma unroll
        for (int j = 0; j < 8; j++) {
            u64 q2 = pack2(qv[j], qv[j]);
            if ((j & 1) == 0) {
                const int s = j >> 1;
#pragma unroll
                for (int p = 0; p < 4; p++)
                    accp[p] = fma2(q2, ke[(p - s) & 3], accp[p]);
            } else {
                const int s = (j + 1) >> 1;
#pragma unroll
                for (int p = 0; p < 4; p++)
                    accp[p] = fma2(q2, ko[(p - s) & 3], accp[p]);
            }
        }
    }

    float acc[8];
#pragma unroll
    for (int p = 0; p < 4; p++) unpack2(accp[p], acc[2 * p], acc[2 * p + 1]);

    const float tsc = temperature[c];
    const float4* vp = (const float4*)&vs[(row0 + m) * QKV_STRIDE + col0];
    float4 va = vp[0], vb = vp[1];
    float vreg[8] = { va.x, va.y, va.z, va.w, vb.x, vb.y, vb.z, vb.w };

    float4 o0, o1;
    o0.x = acc[0] * tsc * vreg[0];
    o0.y = acc[1] * tsc * vreg[1];
    o0.z = acc[2] * tsc * vreg[2];
    o0.w = acc[3] * tsc * vreg[3];
    o1.x = acc[4] * tsc * vreg[4];
    o1.y = acc[5] * tsc * vreg[5];
    o1.z = acc[6] * tsc * vreg[6];
    o1.w = acc[7] * tsc * vreg[7];

    const int gh  = ty0 + row0 + m;
    const int gw0 = tx0 + col0;
    __half* op = (__half*)g_atth + (size_t)bc * HWSZ + (gh << 8) + gw0;
    ulonglong2 st;
    st.x = f4_to_h4(o0);
    st.y = f4_to_h4(o1);
    *(ulonglong2*)op = st;
}

// ---------------------------------------------------------------------------
// K3: out = proj_w(64x64) @ att (fp16 in), f32x2 packed, fp32 out.
// Block: 128 px x 64 oc. blockDim 256 = (tx 0..31 -> 4 px, ty 0..7 -> 4
// oc-pairs = 8 oc).
// ---------------------------------------------------------------------------
__global__ __launch_bounds__(256) void proj_kernel(float* __restrict__ out)
{
    __shared__ u64    ws2[64 * 32];     // [ic][oc_pair]  16KB
    __shared__ float4 xs[64 * 32];      // [ic][px4]      32KB

    const int tid = threadIdx.x;

    for (int i = tid; i < 64 * 32; i += 256)
        ws2[i] = g_wp[i];

    const int base = blockIdx.x * 128;
    const int b  = base >> 16;
    const int hw = base & 65535;
    const __half* xp = (const __half*)g_atth + (size_t)(b * CC) * HWSZ + hw;

    // 1024 jobs: each loads 8 halves (uint4), stores 2 float4s
    for (int i = tid; i < 64 * 16; i += 256) {
        int ic = i >> 4, q = i & 15;
        uint4 u = *(const uint4*)(xp + (size_t)ic * HWSZ + q * 8);
        const __half2* hp = (const __half2*)&u;
        float2 a = __half22float2(hp[0]);
        float2 bb = __half22float2(hp[1]);
        float2 cc = __half22float2(hp[2]);
        float2 dd = __half22float2(hp[3]);
        xs[ic * 32 + 2 * q]     = make_float4(a.x, a.y, bb.x, bb.y);
        xs[ic * 32 + 2 * q + 1] = make_float4(cc.x, cc.y, dd.x, dd.y);
    }
    __syncthreads();

    const int tx = tid & 31, ty = tid >> 5;
    const int ob = ty * 4;                      // 4 oc-pairs = 8 oc

    u64 acc[4][4];
#pragma unroll
    for (int o = 0; o < 4; o++)
#pragma unroll
        for (int p = 0; p < 4; p++) acc[o][p] = 0ull;

#pragma unroll 4
    for (int ic = 0; ic < 64; ic++) {
        float4 xv = xs[ic * 32 + tx];
        u64 xq0 = pack2(xv.x, xv.x);
        u64 xq1 = pack2(xv.y, xv.y);
        u64 xq2 = pack2(xv.z, xv.z);
        u64 xq3 = pack2(xv.w, xv.w);
        const u64* wp = &ws2[ic * 32 + ob];
#pragma unroll
        for (int o = 0; o < 4; o++) {
            u64 wv = wp[o];
            acc[o][0] = fma2(xq0, wv, acc[o][0]);
            acc[o][1] = fma2(xq1, wv, acc[o][1]);
            acc[o][2] = fma2(xq2, wv, acc[o][2]);
            acc[o][3] = fma2(xq3, wv, acc[o][3]);
        }
    }

    float* op = out + (size_t)(b * CC) * HWSZ + hw + tx * 4;
#pragma unroll
    for (int o = 0; o < 4; o++) {
        int oc = 2 * (ob + o);
        float4 lo4, hi4;
        unpack2(acc[o][0], lo4.x, hi4.x);
        unpack2(acc[o][1], lo4.y, hi4.y);
        unpack2(acc[o][2], lo4.z, hi4.z);
        unpack2(acc[o][3], lo4.w, hi4.w);
        *(float4*)(op + (size_t)oc * HWSZ)       = lo4;
        *(float4*)(op + (size_t)(oc + 1) * HWSZ) = hi4;
    }
}

// ---------------------------------------------------------------------------
// Launch
// ---------------------------------------------------------------------------
extern "C" void kernel_launch(void* const* d_in, const int* in_sizes, int n_in,
                              void* d_out, int out_size)
{
    const float* x      = (const float*)d_in[0];
    const float* qkv_w  = (const float*)d_in[1];
    const float* dw_w   = (const float*)d_in[2];
    const float* proj_w = (const float*)d_in[3];
    const float* temp   = (const float*)d_in[4];
    float* out = (float*)d_out;

    pack_w_kernel<<<32, 256>>>(qkv_w, proj_w);    // 8192 threads: 6144 + 2048 pairs
    qkv1x1_kernel<<<8192, 256>>>(x);              // 524288 px / 64
    attn_kernel<<<16384, 256>>>(dw_w, temp);      // 512 (b,c) * 32 tiles
    proj_kernel<<<4096, 256>>>(out);              // 524288 px / 128
}

// round 7
// speedup vs baseline: 2.0845x; 1.0619x over previous
#include <cuda_runtime.h>
#include <cuda_bf16.h>
#include <cuda_fp16.h>
#include <cstdint>

// Problem constants
#define BB   8
#define CC   64
#define HH   256
#define WW   256
#define HWSZ 65536          // 256*256
#define C3   192            // 3*CC

typedef unsigned long long u64;

// Scratch (device globals -- allocation-free rule).  fp16 storage, fp32 math.
__device__ unsigned short g_qkvh[(size_t)BB * C3 * HWSZ];  // 201 MB
__device__ unsigned short g_atth[(size_t)BB * CC * HWSZ];  //  67 MB
__device__ unsigned short g_wqh[C3 * 64];       // fp16 qkv weights [oc][ic]
__device__ u64 g_wp[64 * 32];                   // packed proj weights [ic][oc_pair]

// ---------------------------------------------------------------------------
// packed f32x2 helpers (SASS FFMA2 -- PTX-only path)
// ---------------------------------------------------------------------------
__device__ __forceinline__ u64 pack2(float lo, float hi) {
    u64 r;
    asm("mov.b64 %0, {%1, %2};"
        : "=l"(r) : "r"(__float_as_uint(lo)), "r"(__float_as_uint(hi)));
    return r;
}
__device__ __forceinline__ u64 fma2(u64 a, u64 b, u64 c) {
    u64 d;
    asm("fma.rn.f32x2 %0, %1, %2, %3;" : "=l"(d) : "l"(a), "l"(b), "l"(c));
    return d;
}
__device__ __forceinline__ void unpack2(u64 v, float& lo, float& hi) {
    unsigned int l, h;
    asm("mov.b64 {%0, %1}, %2;" : "=r"(l), "=r"(h) : "l"(v));
    lo = __uint_as_float(l);
    hi = __uint_as_float(h);
}
__device__ __forceinline__ unsigned h2u(__half2 h) { return *(unsigned*)&h; }
__device__ __forceinline__ u64 f4_to_h4(float4 v) {
    unsigned a = h2u(__floats2half2_rn(v.x, v.y));
    unsigned b = h2u(__floats2half2_rn(v.z, v.w));
    return ((u64)b << 32) | a;
}

// HMMA m16n8k16, f16 inputs, f32 accumulate (standard sm_80+ path; works on sm_103)
__device__ __forceinline__ void mma16816(float* c, const unsigned* a, const unsigned* b) {
    asm volatile(
        "mma.sync.aligned.m16n8k16.row.col.f32.f16.f16.f32 "
        "{%0,%1,%2,%3}, {%4,%5,%6,%7}, {%8,%9}, {%0,%1,%2,%3};"
        : "+f"(c[0]), "+f"(c[1]), "+f"(c[2]), "+f"(c[3])
        : "r"(a[0]), "r"(a[1]), "r"(a[2]), "r"(a[3]), "r"(b[0]), "r"(b[1]));
}

// ---------------------------------------------------------------------------
// K0: pack weights once.  g_wqh = plain fp16 [oc][ic]; g_wp = f32x2 pairs.
// ---------------------------------------------------------------------------
__global__ __launch_bounds__(256) void pack_w_kernel(const float* __restrict__ qkv_w,
                                                     const float* __restrict__ proj_w)
{
    int i = blockIdx.x * 256 + threadIdx.x;
    if (i < C3 * 64) {
        g_wqh[i] = __half_as_ushort(__float2half_rn(qkv_w[i]));
    } else if (i < C3 * 64 + 64 * 32) {
        int j = i - C3 * 64;
        int ic = j >> 5, p = j & 31;
        g_wp[j] = pack2(proj_w[(2 * p) * 64 + ic], proj_w[(2 * p + 1) * 64 + ic]);
    }
}

// ---------------------------------------------------------------------------
// K1: qkv via HMMA m16n8k16.  Per CTA: 128 px x 192 oc, K=64.
// 256 threads = 8 warps: warp = (px slab of 32) x (oc half of 96).
// smem: Ws [192][72] f16 (27648B) + Xs [128][72] f16 (18432B) + bounce 8x1280B
// ---------------------------------------------------------------------------
#define WS_BYTES   27648
#define XS_BYTES   18432
#define BOUNCE_OFF (WS_BYTES + XS_BYTES)
#define QKV_SMEM   (BOUNCE_OFF + 8 * 1280)    // 56320

__global__ __launch_bounds__(256) void qkv_hmma_kernel(const float* __restrict__ x)
{
    extern __shared__ __align__(16) char smem[];
    char* Ws = smem;                    // [192][72] halves, row stride 144B
    char* Xs = smem + WS_BYTES;         // [128][72] halves (px-major), stride 144B

    const int tid = threadIdx.x;
    const int base = blockIdx.x * 128;
    const int b  = base >> 16;
    const int hw = base & 65535;

    // Fill Ws: 1536 uint4 jobs (8 halves each)
    for (int i = tid; i < 1536; i += 256) {
        uint4 v = ((const uint4*)g_wqh)[i];
        int oc = i >> 3, blk = i & 7;
        *(uint4*)(Ws + oc * 144 + blk * 16) = v;
    }

    // Fill Xs: transpose x[ic][px] fp32 -> Xs[px][ic] fp16.  4096 jobs.
    const float* xp = x + (size_t)(b * CC) * HWSZ + hw;
    for (int i = tid; i < 4096; i += 256) {
        int ic2 = i >> 7, px = i & 127;
        float f0 = xp[(size_t)(2 * ic2) * HWSZ + px];
        float f1 = xp[(size_t)(2 * ic2 + 1) * HWSZ + px];
        *(unsigned*)(Xs + px * 144 + ic2 * 4) = h2u(__floats2half2_rn(f0, f1));
    }
    __syncthreads();

    const int wid  = tid >> 5, lane = tid & 31;
    const int slab = wid & 3;            // px slab (32 px)
    const int mside = wid >> 1 >> 1;     // 0 or 1 (oc 0-95 / 96-191)
    const int g = lane >> 2, t = lane & 3;
    const int pxb = slab * 32;
    char* bb = smem + BOUNCE_OFF + wid * 1280;   // warp-private bounce [16][40] halves
    __half* qh = (__half*)g_qkvh;

#pragma unroll 1
    for (int h = 0; h < 2; h++) {                // two passes of 3 m-tiles
        float acc[3][4][4];
#pragma unroll
        for (int j = 0; j < 3; j++)
#pragma unroll
            for (int n = 0; n < 4; n++)
#pragma unroll
                for (int q = 0; q < 4; q++) acc[j][n][q] = 0.f;

#pragma unroll
        for (int kk = 0; kk < 4; kk++) {
            unsigned a[3][4], bfr[4][2];
#pragma unroll
            for (int j = 0; j < 3; j++) {
                int row = mside * 96 + (h * 3 + j) * 16 + g;
                const char* p0 = Ws + row * 144 + kk * 32 + t * 4;
                a[j][0] = *(const unsigned*)(p0);
                a[j][1] = *(const unsigned*)(p0 + 8 * 144);
                a[j][2] = *(const unsigned*)(p0 + 16);
                a[j][3] = *(const unsigned*)(p0 + 8 * 144 + 16);
            }
#pragma unroll
            for (int n = 0; n < 4; n++) {
                int px = pxb + n * 8 + g;
                const char* p0 = Xs + px * 144 + kk * 32 + t * 4;
                bfr[n][0] = *(const unsigned*)(p0);
                bfr[n][1] = *(const unsigned*)(p0 + 16);
            }
#pragma unroll
            for (int j = 0; j < 3; j++)
#pragma unroll
                for (int n = 0; n < 4; n++)
                    mma16816(acc[j][n], a[j], bfr[n]);
        }

        // epilogue: per m-tile bounce -> coalesced u64 stores
#pragma unroll 1
        for (int j = 0; j < 3; j++) {
#pragma unroll
            for (int n = 0; n < 4; n++) {
                unsigned lo = h2u(__floats2half2_rn(acc[j][n][0], acc[j][n][1]));
                unsigned hi = h2u(__floats2half2_rn(acc[j][n][2], acc[j][n][3]));
                *(unsigned*)(bb + g * 80 + n * 16 + t * 4)       = lo;
                *(unsigned*)(bb + (g + 8) * 80 + n * 16 + t * 4) = hi;
            }
            __syncwarp();
            int oc0 = mside * 96 + (h * 3 + j) * 16;
#pragma unroll
            for (int p = 0; p < 4; p++) {
                int r = (lane >> 3) + p * 4;
                u64 v = *(u64*)(bb + r * 80 + (lane & 7) * 8);
                __half* dst = qh + (size_t)(b * C3 + oc0 + r) * HWSZ
                            + hw + pxb + (lane & 7) * 4;
                *(u64*)dst = v;
            }
            __syncwarp();
        }
    }
}

// ---------------------------------------------------------------------------
// K2: depthwise 3x3 (f32x2 sliding window) + 8x8 circular-conv attention
//     + temperature + v gate.  One block = one (b,c) and a 64x32 pixel tile.
// ---------------------------------------------------------------------------
#define QKV_STRIDE 68
#define QKV_CH     2176        // 32 * 68
#define QOFF 0
#define KOFF 2176
#define VOFF 4352

__global__ __launch_bounds__(256) void attn_kernel(const float* __restrict__ dw_w,
                                                   const float* __restrict__ temperature)
{
    __shared__ float sm[6732];          // phase A: halo (3 x 34 x 66); phase C/D: q/k/v (3 x 2176)
    __shared__ u64   dws2[27];          // (w,w) packed depthwise taps

    const int tid  = threadIdx.x;
    const int bc   = blockIdx.x >> 5;            // 0..511
    const int tile = blockIdx.x & 31;            // 0..31 (4 across x 8 down)
    const int b = bc >> 6;
    const int c = bc & 63;
    const int tx0 = (tile & 3) * 64;
    const int ty0 = (tile >> 2) * 32;

    if (tid < 27) {
        int ch = tid / 9, tap = tid - ch * 9;
        float wv = dw_w[(c + (ch << 6)) * 9 + tap];
        dws2[tid] = pack2(wv, wv);
    }

    const __half* qbase = (const __half*)g_qkvh;

    // Phase A interior: 816 vector jobs (3 ch x 34 rows x 8 uint4/row)
    for (int i = tid; i < 816; i += 256) {
        int ch  = i / 272;
        int rem = i - ch * 272;
        int hy  = rem >> 3, v8 = rem & 7;
        int gh  = ty0 + hy - 1;
        float f0, f1, f2, f3, f4, f5, f6, f7;
        if ((unsigned)gh < 256u) {
            const __half* gp = qbase + (size_t)(b * C3 + c + (ch << 6)) * HWSZ
                             + (gh << 8) + tx0 + v8 * 8;
            uint4 u = *(const uint4*)gp;
            const __half2* hp = (const __half2*)&u;
            float2 a = __half22float2(hp[0]);
            float2 bb = __half22float2(hp[1]);
            float2 cc = __half22float2(hp[2]);
            float2 dd = __half22float2(hp[3]);
            f0 = a.x;  f1 = a.y;  f2 = bb.x; f3 = bb.y;
            f4 = cc.x; f5 = cc.y; f6 = dd.x; f7 = dd.y;
        } else {
            f0 = f1 = f2 = f3 = f4 = f5 = f6 = f7 = 0.f;
        }
        float* sp = sm + ch * 2244 + hy * 66 + 1 + v8 * 8;
        sp[0] = f0;
        *(float2*)(sp + 1) = make_float2(f1, f2);
        *(float2*)(sp + 3) = make_float2(f3, f4);
        *(float2*)(sp + 5) = make_float2(f5, f6);
        sp[7] = f7;
    }
    // Phase A edges: 204 jobs (3 ch x 34 rows x 2 sides)
    if (tid < 204) {
        int rc = tid >> 1, side = tid & 1;
        int ch = rc / 34, hy = rc - ch * 34;
        int gh = ty0 + hy - 1;
        int gw = side ? (tx0 + 64) : (tx0 - 1);
        float v = 0.f;
        if ((unsigned)gh < 256u && (unsigned)gw < 256u)
            v = __half2float(qbase[(size_t)(b * C3 + c + (ch << 6)) * HWSZ + (gh << 8) + gw]);
        sm[ch * 2244 + hy * 66 + (side ? 65 : 0)] = v;
    }
    __syncthreads();

    // Phase B: depthwise 3x3, f32x2 column pairs with vertical sliding window.
    u64 acc2[16];
    const int jch = tid >> 6;           // valid when tid < 192
    const int jrem = tid & 63;
    const int jc   = (jrem & 31) * 2;   // output col (even)
    const int jr0  = (jrem >> 5) * 16;  // output row base
    if (tid < 192) {
#pragma unroll
        for (int i = 0; i < 16; i++) acc2[i] = 0ull;
        const float* hbase = sm + jch * 2244 + jr0 * 66 + jc;
        const u64* w2 = &dws2[jch * 9];
#pragma unroll
        for (int hy = 0; hy < 18; hy++) {
            u64 A = *(const u64*)(hbase + hy * 66);       // (h[c], h[c+1])
            u64 B = *(const u64*)(hbase + hy * 66 + 2);   // (h[c+2], h[c+3])
            float alo, ahi, blo, bhi;
            unpack2(A, alo, ahi);
            unpack2(B, blo, bhi);
            u64 M1 = pack2(ahi, blo);                      // (h[c+1], h[c+2])
#pragma unroll
            for (int kh = 0; kh < 3; kh++) {
                int r = hy - kh;
                if (r >= 0 && r < 16) {
                    acc2[r] = fma2(A,  w2[kh * 3 + 0], acc2[r]);
                    acc2[r] = fma2(M1, w2[kh * 3 + 1], acc2[r]);
                    acc2[r] = fma2(B,  w2[kh * 3 + 2], acc2[r]);
                }
            }
        }
    }
    __syncthreads();

    // Phase C: store q/k/v in stride-68 layout
    if (tid < 192) {
        float* dst = sm + jch * QKV_CH + jr0 * QKV_STRIDE + jc;
#pragma unroll
        for (int i = 0; i < 16; i++)
            *(u64*)(dst + i * QKV_STRIDE) = acc2[i];
    }
    __syncthreads();

    const float* qs = sm + QOFF;        // [32][68]
    const float* ks = sm + KOFF;
    const float* vs = sm + VOFF;

    // Phase D: 8x8 circular conv, f32x2 packed.  32 patches x 8 rows = 256 jobs.
    const int m     = tid & 7;
    const int patch = tid >> 3;
    const int pxi   = patch & 7;
    const int pyi   = patch >> 3;
    const int row0  = pyi * 8;
    const int col0  = pxi * 8;

    u64 accp[4];        // accp[p] = (acc[2p], acc[2p+1])
#pragma unroll
    for (int p = 0; p < 4; p++) accp[p] = 0ull;

#pragma unroll
    for (int i = 0; i < 8; i++) {
        int kr = (m - i) & 7;
        const float4* kp = (const float4*)&ks[(row0 + kr) * QKV_STRIDE + col0];
        float4 ka = kp[0], kb = kp[1];
        float k0 = ka.x, k1 = ka.y, k2 = ka.z, k3 = ka.w;
        float k4 = kb.x, k5 = kb.y, k6 = kb.z, k7 = kb.w;
        u64 ke[4] = { pack2(k0, k1), pack2(k2, k3), pack2(k4, k5), pack2(k6, k7) };
        u64 ko[4] = { pack2(k1, k2), pack2(k3, k4), pack2(k5, k6), pack2(k7, k0) };

        const float4* qp = (const float4*)&qs[(row0 + i) * QKV_STRIDE + col0];
        float4 qa = qp[0], qb = qp[1];
        float qv[8] = { qa.x, qa.y, qa.z, qa.w, qb.x, qb.y, qb.z, qb.w };

#pragma unroll
        for (int j = 0; j < 8; j++) {
            u64 q2 = pack2(qv[j], qv[j]);
            if ((j & 1) == 0) {
                const int s = j >> 1;
#pragma unroll
                for (int p = 0; p < 4; p++)
                    accp[p] = fma2(q2, ke[(p - s) & 3], accp[p]);
            } else {
                const int s = (j + 1) >> 1;
#pragma unroll
                for (int p = 0; p < 4; p++)
                    accp[p] = fma2(q2, ko[(p - s) & 3], accp[p]);
            }
        }
    }

    float acc[8];
#pragma unroll
    for (int p = 0; p < 4; p++) unpack2(accp[p], acc[2 * p], acc[2 * p + 1]);

    const float tsc = temperature[c];
    const float4* vp = (const float4*)&vs[(row0 + m) * QKV_STRIDE + col0];
    float4 va = vp[0], vb = vp[1];
    float vreg[8] = { va.x, va.y, va.z, va.w, vb.x, vb.y, vb.z, vb.w };

    float4 o0, o1;
    o0.x = acc[0] * tsc * vreg[0];
    o0.y = acc[1] * tsc * vreg[1];
    o0.z = acc[2] * tsc * vreg[2];
    o0.w = acc[3] * tsc * vreg[3];
    o1.x = acc[4] * tsc * vreg[4];
    o1.y = acc[5] * tsc * vreg[5];
    o1.z = acc[6] * tsc * vreg[6];
    o1.w = acc[7] * tsc * vreg[7];

    const int gh  = ty0 + row0 + m;
    const int gw0 = tx0 + col0;
    __half* op = (__half*)g_atth + (size_t)bc * HWSZ + (gh << 8) + gw0;
    ulonglong2 st;
    st.x = f4_to_h4(o0);
    st.y = f4_to_h4(o1);
    *(ulonglong2*)op = st;
}

// ---------------------------------------------------------------------------
// K3: out = proj_w(64x64) @ att (fp16 in), f32x2 packed, fp32 out.
// ---------------------------------------------------------------------------
__global__ __launch_bounds__(256) void proj_kernel(float* __restrict__ out)
{
    __shared__ u64    ws2[64 * 32];     // [ic][oc_pair]  16KB
    __shared__ float4 xs[64 * 32];      // [ic][px4]      32KB

    const int tid = threadIdx.x;

    for (int i = tid; i < 64 * 32; i += 256)
        ws2[i] = g_wp[i];

    const int base = blockIdx.x * 128;
    const int b  = base >> 16;
    const int hw = base & 65535;
    const __half* xp = (const __half*)g_atth + (size_t)(b * CC) * HWSZ + hw;

    for (int i = tid; i < 64 * 16; i += 256) {
        int ic = i >> 4, q = i & 15;
        uint4 u = *(const uint4*)(xp + (size_t)ic * HWSZ + q * 8);
        const __half2* hp = (const __half2*)&u;
        float2 a = __half22float2(hp[0]);
        float2 bb = __half22float2(hp[1]);
        float2 cc = __half22float2(hp[2]);
        float2 dd = __half22float2(hp[3]);
        xs[ic * 32 + 2 * q]     = make_float4(a.x, a.y, bb.x, bb.y);
        xs[ic * 32 + 2 * q + 1] = make_float4(cc.x, cc.y, dd.x, dd.y);
    }
    __syncthreads();

    const int tx = tid & 31, ty = tid >> 5;
    const int ob = ty * 4;                      // 4 oc-pairs = 8 oc

    u64 acc[4][4];
#pragma unroll
    for (int o = 0; o < 4; o++)
#pragma unroll
        for (int p = 0; p < 4; p++) acc[o][p] = 0ull;

#pragma unroll 4
    for (int ic = 0; ic < 64; ic++) {
        float4 xv = xs[ic * 32 + tx];
        u64 xq0 = pack2(xv.x, xv.x);
        u64 xq1 = pack2(xv.y, xv.y);
        u64 xq2 = pack2(xv.z, xv.z);
        u64 xq3 = pack2(xv.w, xv.w);
        const u64* wp = &ws2[ic * 32 + ob];
#pragma unroll
        for (int o = 0; o < 4; o++) {
            u64 wv = wp[o];
            acc[o][0] = fma2(xq0, wv, acc[o][0]);
            acc[o][1] = fma2(xq1, wv, acc[o][1]);
            acc[o][2] = fma2(xq2, wv, acc[o][2]);
            acc[o][3] = fma2(xq3, wv, acc[o][3]);
        }
    }

    float* op = out + (size_t)(b * CC) * HWSZ + hw + tx * 4;
#pragma unroll
    for (int o = 0; o < 4; o++) {
        int oc = 2 * (ob + o);
        float4 lo4, hi4;
        unpack2(acc[o][0], lo4.x, hi4.x);
        unpack2(acc[o][1], lo4.y, hi4.y);
        unpack2(acc[o][2], lo4.z, hi4.z);
        unpack2(acc[o][3], lo4.w, hi4.w);
        *(float4*)(op + (size_t)oc * HWSZ)       = lo4;
        *(float4*)(op + (size_t)(oc + 1) * HWSZ) = hi4;
    }
}

// ---------------------------------------------------------------------------
// Launch
// ---------------------------------------------------------------------------
extern "C" void kernel_launch(void* const* d_in, const int* in_sizes, int n_in,
                              void* d_out, int out_size)
{
    const float* x      = (const float*)d_in[0];
    const float* qkv_w  = (const float*)d_in[1];
    const float* dw_w   = (const float*)d_in[2];
    const float* proj_w = (const float*)d_in[3];
    const float* temp   = (const float*)d_in[4];
    float* out = (float*)d_out;

    cudaFuncSetAttribute(qkv_hmma_kernel,
                         cudaFuncAttributeMaxDynamicSharedMemorySize, QKV_SMEM);

    pack_w_kernel<<<56, 256>>>(qkv_w, proj_w);          // 12288 + 2048 jobs
    qkv_hmma_kernel<<<4096, 256, QKV_SMEM>>>(x);        // 524288 px / 128
    attn_kernel<<<16384, 256>>>(dw_w, temp);            // 512 (b,c) * 32 tiles
    proj_kernel<<<4096, 256>>>(out);                    // 524288 px / 128
}